// round 13
// baseline (speedup 1.0000x reference)
#include <cuda_runtime.h>
#include <cuda_fp16.h>

// Problem constants (dataset: N=100000, E=800000, D=3, H=4, F=32)
#define NMAX 100000
#define EMAX 800000
#define ETMAX (NMAX + EMAX)

// ---------------- device scratch (static: no allocation allowed) -------------
__device__ __half d_hh[(size_t)NMAX * 128];    // per-layer hidden [N,4,32] fp16
__device__ float4 d_as[NMAX];                  // attention src logits [N,4]
__device__ float4 d_ad[NMAX];                  // attention dst logits [N,4]
__device__ float  d_xa[(size_t)NMAX * 32];     // layer outputs ping (fp32)
__device__ float  d_xb[(size_t)NMAX * 32];     // layer outputs pong (fp32)
__device__ int    d_rowptr[NMAX + 1];
__device__ int    d_cnt[NMAX];
__device__ int    d_wp[NMAX];
__device__ int    d_col[ETMAX];
__device__ int    d_tmask[NMAX];
__device__ int    d_trank[NMAX];
__device__ int    d_bsums0[1024];
__device__ int    d_bsums1[1024];
__device__ int    d_total[1];
__device__ int    d_is64[1];

// grid barrier state (self-resetting; generation persists across calls)
__device__ unsigned d_barcnt = 0;
__device__ unsigned d_bargen = 0;

__device__ __forceinline__ void gsync(int nb) {
    __syncthreads();
    if (threadIdx.x == 0) {
        __threadfence();
        unsigned g = d_bargen;
        unsigned a = atomicAdd(&d_barcnt, 1u);
        if (a == (unsigned)nb - 1u) {
            d_barcnt = 0;
            __threadfence();
            atomicAdd(&d_bargen, 1u);
        } else {
            while (atomicAdd(&d_bargen, 0u) == g) __nanosleep(128);
        }
        __threadfence();
    }
    __syncthreads();
}

__device__ __forceinline__ float lk(float v, float s) { return v >= 0.f ? v : s * v; }

__device__ __forceinline__ int eidx(const void* ei, int i) {
    if (d_is64[0]) return (int)((const long long*)ei)[i];
    return ((const int*)ei)[i];
}

// 256-wide exclusive scan in shared ints; exclusive prefix returned; total in s[255]
__device__ __forceinline__ int bscan(int v, int* s) {
    int tid = threadIdx.x;
    s[tid] = v;
    __syncthreads();
    for (int off = 1; off < 256; off <<= 1) {
        int t = (tid >= off) ? s[tid - off] : 0;
        __syncthreads();
        s[tid] += t;
        __syncthreads();
    }
    return s[tid] - v;
}

// One MLP GEMM layer on a 64-node tile held in shared memory.
template <int K>
__device__ __forceinline__ void mlp_layer(float* s, int inO, int inS, int outO, int outS,
                                          int wO, int bO, int tx, int ty, int nn) {
    float a0[4], a1[4];
#pragma unroll
    for (int j = 0; j < 4; j++) { a0[j] = s[bO + tx * 4 + j]; a1[j] = a0[j]; }
#pragma unroll
    for (int k = 0; k < K; k++) {
        float4 w = *(const float4*)&s[wO + k * 32 + tx * 4];
        float x0 = s[inO + (ty * 2) * inS + k];
        float x1 = s[inO + (ty * 2 + 1) * inS + k];
        a0[0] = fmaf(x0, w.x, a0[0]); a1[0] = fmaf(x1, w.x, a1[0]);
        a0[1] = fmaf(x0, w.y, a0[1]); a1[1] = fmaf(x1, w.y, a1[1]);
        a0[2] = fmaf(x0, w.z, a0[2]); a1[2] = fmaf(x1, w.z, a1[2]);
        a0[3] = fmaf(x0, w.w, a0[3]); a1[3] = fmaf(x1, w.w, a1[3]);
    }
    __syncthreads();
    if (ty * 2 < nn) {
#pragma unroll
        for (int j = 0; j < 4; j++) s[outO + (ty * 2) * outS + tx * 4 + j] = lk(a0[j], 0.01f);
    }
    if (ty * 2 + 1 < nn) {
#pragma unroll
        for (int j = 0; j < 4; j++) s[outO + (ty * 2 + 1) * outS + tx * 4 + j] = lk(a1[j], 0.01f);
    }
    __syncthreads();
}

struct Params {
    const float* x; const void* ei;
    const float* W0;  const float* W1;  const float* W2;
    const float* aS0; const float* aS1; const float* aS2;
    const float* aD0; const float* aD1; const float* aD2;
    const float* b0;  const float* b1;  const float* b2;
    const float* mW1; const float* mb1; const float* mW2; const float* mb2;
    const float* mW3; const float* mb3; const float* mW4; const float* mb4;
    const float* mW5; const float* mb5;
    float* out; int N; int E;
};

__global__ __launch_bounds__(256, 4) void k_mega(Params p) {
    __shared__ float s_f[9216];
    int* s_i = (int*)s_f;
    const int tid = threadIdx.x;
    const int nb = gridDim.x;
    const int gthreads = nb * 256;
    const int gid = blockIdx.x * 256 + tid;
    const int lane = tid & 31;
    const int wid = tid >> 5;
    const int gw = blockIdx.x * 8 + wid;
    const int nw = nb * 8;
    const int N = p.N, E = p.E, ET = E + N;
    const int R = (N + nb - 1) / nb;

    // ---- P0: init counters + tower mask; detect edge dtype -----------------
    for (int i = gid; i < N; i += gthreads) {
        d_cnt[i] = 0;
        d_tmask[i] = (p.x[i * 3] == 0.0f) ? 1 : 0;
    }
    if (blockIdx.x == 0) {
        int bad = 0;
        if (tid < 128) bad = (((const int*)p.ei)[2 * tid + 1] != 0) ? 1 : 0;
        s_i[tid] = bad;
        __syncthreads();
        if (tid == 0) {
            int any = 0;
            for (int i = 0; i < 128; i++) any |= s_i[i];
            d_is64[0] = any ? 0 : 1;
        }
    }
    gsync(nb);

    // ---- P1: degree count ---------------------------------------------------
    for (int e = gid; e < ET; e += gthreads) {
        int dst = (e < E) ? eidx(p.ei, E + e) : (e - E);
        atomicAdd(&d_cnt[dst], 1);
    }
    gsync(nb);

    // ---- P2a: per-block range sums (cnt and tmask) --------------------------
    {
        int lo = blockIdx.x * R, hi = min(N, lo + R);
        int s0 = 0, s1 = 0;
        for (int i = lo + tid; i < hi; i += 256) { s0 += d_cnt[i]; s1 += d_tmask[i]; }
#pragma unroll
        for (int o = 16; o; o >>= 1) {
            s0 += __shfl_xor_sync(0xffffffffu, s0, o);
            s1 += __shfl_xor_sync(0xffffffffu, s1, o);
        }
        if (lane == 0) { s_i[wid] = s0; s_i[8 + wid] = s1; }
        __syncthreads();
        if (tid == 0) {
            int a = 0, b = 0;
            for (int w = 0; w < 8; w++) { a += s_i[w]; b += s_i[8 + w]; }
            d_bsums0[blockIdx.x] = a; d_bsums1[blockIdx.x] = b;
        }
    }
    gsync(nb);

    // ---- P2b: block 0 scans the block sums ----------------------------------
    if (blockIdx.x == 0) {
        for (int arr = 0; arr < 2; arr++) {
            int* bs = arr ? d_bsums1 : d_bsums0;
            int carry = 0;
            for (int c = 0; c < nb; c += 256) {
                int i = c + tid;
                int v = (i < nb) ? bs[i] : 0;
                int ex = bscan(v, s_i);
                int tot = s_i[255];
                if (i < nb) bs[i] = carry + ex;
                carry += tot;
                __syncthreads();
            }
            if (tid == 0) { if (arr == 0) d_rowptr[N] = carry; else d_total[0] = carry; }
        }
    }
    gsync(nb);

    // ---- P2c: per-block local scan + global offset --------------------------
    {
        int lo = blockIdx.x * R, hi = min(N, lo + R);
        for (int arr = 0; arr < 2; arr++) {
            const int* in = arr ? d_tmask : d_cnt;
            int carry = arr ? d_bsums1[blockIdx.x] : d_bsums0[blockIdx.x];
            for (int c = lo; c < hi; c += 256) {
                int i = c + tid;
                int v = (i < hi) ? in[i] : 0;
                int ex = bscan(v, s_i);
                int tot = s_i[255];
                if (i < hi) {
                    int o = carry + ex;
                    if (arr == 0) { d_rowptr[i] = o; d_wp[i] = o; }
                    else d_trank[i] = o;
                }
                carry += tot;
                __syncthreads();
            }
        }
    }
    gsync(nb);

    // ---- P3: CSR fill -------------------------------------------------------
    for (int e = gid; e < ET; e += gthreads) {
        int src, dst;
        if (e < E) { src = eidx(p.ei, e); dst = eidx(p.ei, E + e); }
        else       { src = dst = e - E; }
        int pp = atomicAdd(&d_wp[dst], 1);
        d_col[pp] = src;
    }
    gsync(nb);

    // ---- P4: three GAT layers ----------------------------------------------
    for (int L = 0; L < 3; L++) {
        const int din = (L == 0) ? 3 : 32;
        const float* W  = (L == 0) ? p.W0  : (L == 1) ? p.W1  : p.W2;
        const float* aS = (L == 0) ? p.aS0 : (L == 1) ? p.aS1 : p.aS2;
        const float* aD = (L == 0) ? p.aD0 : (L == 1) ? p.aD1 : p.aD2;
        const float* bs = (L == 0) ? p.b0  : (L == 1) ? p.b1  : p.b2;
        const float* xin = (L == 0) ? p.x : (L == 1) ? d_xa : d_xb;
        float* xout = (L == 1) ? d_xb : d_xa;

        // P4a: h = x@W fused with attention logits (fp32 accs; h stored fp16)
        for (int i = tid; i < din * 128; i += 256) s_f[i] = W[i];
        if (tid < 128) { s_f[4096 + tid] = aS[tid]; s_f[4224 + tid] = aD[tid]; }
        __syncthreads();

        if (din == 3) {
            for (int node = gw; node < N; node += nw) {
                float xr = (lane < 3) ? xin[node * 3 + lane] : 0.f;
                float asv[4], adv[4];
#pragma unroll
                for (int hd4 = 0; hd4 < 4; hd4++) {
                    float s = 0.f;
#pragma unroll
                    for (int k = 0; k < 3; k++)
                        s = fmaf(__shfl_sync(0xffffffffu, xr, k), s_f[k * 128 + hd4 * 32 + lane], s);
                    // pack lane pairs into half2 stores (even lanes write)
                    float s1 = __shfl_down_sync(0xffffffffu, s, 1);
                    if (!(lane & 1)) {
                        __half2 hv = __floats2half2_rn(s, s1);
                        *(__half2*)(d_hh + node * 128 + hd4 * 32 + lane) = hv;
                    }
                    float u = s * s_f[4096 + hd4 * 32 + lane];
                    float v = s * s_f[4224 + hd4 * 32 + lane];
#pragma unroll
                    for (int o = 16; o; o >>= 1) {
                        u += __shfl_xor_sync(0xffffffffu, u, o);
                        v += __shfl_xor_sync(0xffffffffu, v, o);
                    }
                    asv[hd4] = u; adv[hd4] = v;
                }
                if (lane == 0) {
                    d_as[node] = make_float4(asv[0], asv[1], asv[2], asv[3]);
                    d_ad[node] = make_float4(adv[0], adv[1], adv[2], adv[3]);
                }
            }
        } else {
            // tiled GEMM: 32-node x 128-out tile, thread = 2 nodes x 8 outs
            const int XO = 4352;                 // Xs[32][33]
            const int tx = tid & 15, ty = tid >> 4;
            int ntile = (N + 31) / 32;
            for (int t = blockIdx.x; t < ntile; t += nb) {
                int n0 = t * 32, nn = min(32, N - n0);
                __syncthreads();
                for (int i = tid; i < nn * 8; i += 256) {
                    float4 v = ((const float4*)(xin + n0 * 32))[i];
                    int r = (i * 4) >> 5, c = (i * 4) & 31;
                    float* xr = s_f + XO + r * 33 + c;
                    xr[0] = v.x; xr[1] = v.y; xr[2] = v.z; xr[3] = v.w;
                }
                __syncthreads();
                float acc[2][8];
#pragma unroll
                for (int i = 0; i < 2; i++)
#pragma unroll
                    for (int j = 0; j < 8; j++) acc[i][j] = 0.f;
#pragma unroll
                for (int k = 0; k < 32; k++) {
                    float4 w0 = *(const float4*)&s_f[k * 128 + tx * 8];
                    float4 w1 = *(const float4*)&s_f[k * 128 + tx * 8 + 4];
                    float x0 = s_f[XO + (ty * 2) * 33 + k];
                    float x1 = s_f[XO + (ty * 2 + 1) * 33 + k];
                    acc[0][0] = fmaf(x0, w0.x, acc[0][0]); acc[1][0] = fmaf(x1, w0.x, acc[1][0]);
                    acc[0][1] = fmaf(x0, w0.y, acc[0][1]); acc[1][1] = fmaf(x1, w0.y, acc[1][1]);
                    acc[0][2] = fmaf(x0, w0.z, acc[0][2]); acc[1][2] = fmaf(x1, w0.z, acc[1][2]);
                    acc[0][3] = fmaf(x0, w0.w, acc[0][3]); acc[1][3] = fmaf(x1, w0.w, acc[1][3]);
                    acc[0][4] = fmaf(x0, w1.x, acc[0][4]); acc[1][4] = fmaf(x1, w1.x, acc[1][4]);
                    acc[0][5] = fmaf(x0, w1.y, acc[0][5]); acc[1][5] = fmaf(x1, w1.y, acc[1][5]);
                    acc[0][6] = fmaf(x0, w1.z, acc[0][6]); acc[1][6] = fmaf(x1, w1.z, acc[1][6]);
                    acc[0][7] = fmaf(x0, w1.w, acc[0][7]); acc[1][7] = fmaf(x1, w1.w, acc[1][7]);
                }
#pragma unroll
                for (int i = 0; i < 2; i++) {
                    int nl = ty * 2 + i;
                    int node = n0 + nl;
                    bool ok = nl < nn;
                    if (ok) {
                        __half2 q0 = __floats2half2_rn(acc[i][0], acc[i][1]);
                        __half2 q1 = __floats2half2_rn(acc[i][2], acc[i][3]);
                        __half2 q2 = __floats2half2_rn(acc[i][4], acc[i][5]);
                        __half2 q3 = __floats2half2_rn(acc[i][6], acc[i][7]);
                        uint4 pk;
                        pk.x = reinterpret_cast<unsigned&>(q0);
                        pk.y = reinterpret_cast<unsigned&>(q1);
                        pk.z = reinterpret_cast<unsigned&>(q2);
                        pk.w = reinterpret_cast<unsigned&>(q3);
                        *(uint4*)(d_hh + node * 128 + tx * 8) = pk;
                    }
                    float u = 0.f, v = 0.f;
#pragma unroll
                    for (int j = 0; j < 8; j++) {
                        u = fmaf(acc[i][j], s_f[4096 + tx * 8 + j], u);
                        v = fmaf(acc[i][j], s_f[4224 + tx * 8 + j], v);
                    }
                    u += __shfl_xor_sync(0xffffffffu, u, 1);
                    u += __shfl_xor_sync(0xffffffffu, u, 2);
                    v += __shfl_xor_sync(0xffffffffu, v, 1);
                    v += __shfl_xor_sync(0xffffffffu, v, 2);
                    if (ok && (tid & 3) == 0) {
                        int head = tx >> 2;
                        ((float*)&d_as[node])[head] = u;
                        ((float*)&d_ad[node])[head] = v;
                    }
                }
            }
        }
        gsync(nb);

        // P4c: half-warp per node; single-pass exp + gather, normalize after.
        // Logits O(+-5): exp cannot overflow; softmax is shift-invariant, and
        // (sum ex*h)/(sum ex + 1e-16) == sum (ex/denom)*h exactly in math.
        // fp16 h row = 256B = 16 lanes x uint4; one LDG.128 advances 2 nodes.
        if (tid < 32) s_f[tid] = bs[tid];
        __syncthreads();
        const int hw = lane >> 4;                  // half-warp id (node parity)
        const int hlane = lane & 15;
        const unsigned hmask = 0xFFFFu << (hw * 16);
        const int hd = hlane >> 2;                 // head of this lane
        const int loff = hd * 32 + (hlane & 3) * 8;  // half offset within row
        // per-warp packed buffers: [2 halves][4 heads][17] float2 {ex, colbits}
        float2* pb = (float2*)(s_f + 128) + wid * 136 + hw * 68;
        const float2* pbh = pb + hd * 17;
        const int half_n = (N + 1) >> 1;
        for (int nn2 = gw; nn2 < half_n; nn2 += nw) {
            int node = nn2 * 2 + hw;
            bool valid = node < N;
            int beg = 0, end = 0;
            if (valid) { beg = d_rowptr[node]; end = d_rowptr[node + 1]; }
            float4 ad = valid ? d_ad[node] : make_float4(0.f, 0.f, 0.f, 0.f);
            float acc[8];
#pragma unroll
            for (int j = 0; j < 8; j++) acc[j] = 0.f;
            float se0 = 0.f, se1 = 0.f, se2 = 0.f, se3 = 0.f;
            for (int base = beg; base < end; base += 16) {
                int m = min(16, end - base);
                if (hlane < m) {
                    int c = d_col[base + hlane];
                    float4 a = d_as[c];
                    float4 ex;
                    ex.x = __expf(lk(a.x + ad.x, 0.2f));
                    ex.y = __expf(lk(a.y + ad.y, 0.2f));
                    ex.z = __expf(lk(a.z + ad.z, 0.2f));
                    ex.w = __expf(lk(a.w + ad.w, 0.2f));
                    se0 += ex.x; se1 += ex.y; se2 += ex.z; se3 += ex.w;
                    float cf = __int_as_float(c);
                    pb[0 * 17 + hlane] = make_float2(ex.x, cf);
                    pb[1 * 17 + hlane] = make_float2(ex.y, cf);
                    pb[2 * 17 + hlane] = make_float2(ex.z, cf);
                    pb[3 * 17 + hlane] = make_float2(ex.w, cf);
                }
                __syncwarp(hmask);
                int e = 0;
                for (; e + 1 < m; e += 2) {
                    float2 p0 = pbh[e], p1 = pbh[e + 1];
                    uint4 v0 = *(const uint4*)(d_hh + __float_as_int(p0.y) * 128 + loff);
                    uint4 v1 = *(const uint4*)(d_hh + __float_as_int(p1.y) * 128 + loff);
                    float2 a0 = __half22float2(reinterpret_cast<__half2&>(v0.x));
                    float2 a1 = __half22float2(reinterpret_cast<__half2&>(v0.y));
                    float2 a2 = __half22float2(reinterpret_cast<__half2&>(v0.z));
                    float2 a3 = __half22float2(reinterpret_cast<__half2&>(v0.w));
                    float2 b0 = __half22float2(reinterpret_cast<__half2&>(v1.x));
                    float2 b1 = __half22float2(reinterpret_cast<__half2&>(v1.y));
                    float2 b2 = __half22float2(reinterpret_cast<__half2&>(v1.z));
                    float2 b3 = __half22float2(reinterpret_cast<__half2&>(v1.w));
                    acc[0] = fmaf(p0.x, a0.x, acc[0]); acc[1] = fmaf(p0.x, a0.y, acc[1]);
                    acc[2] = fmaf(p0.x, a1.x, acc[2]); acc[3] = fmaf(p0.x, a1.y, acc[3]);
                    acc[4] = fmaf(p0.x, a2.x, acc[4]); acc[5] = fmaf(p0.x, a2.y, acc[5]);
                    acc[6] = fmaf(p0.x, a3.x, acc[6]); acc[7] = fmaf(p0.x, a3.y, acc[7]);
                    acc[0] = fmaf(p1.x, b0.x, acc[0]); acc[1] = fmaf(p1.x, b0.y, acc[1]);
                    acc[2] = fmaf(p1.x, b1.x, acc[2]); acc[3] = fmaf(p1.x, b1.y, acc[3]);
                    acc[4] = fmaf(p1.x, b2.x, acc[4]); acc[5] = fmaf(p1.x, b2.y, acc[5]);
                    acc[6] = fmaf(p1.x, b3.x, acc[6]); acc[7] = fmaf(p1.x, b3.y, acc[7]);
                }
                if (e < m) {
                    float2 p0 = pbh[e];
                    uint4 v0 = *(const uint4*)(d_hh + __float_as_int(p0.y) * 128 + loff);
                    float2 a0 = __half22float2(reinterpret_cast<__half2&>(v0.x));
                    float2 a1 = __half22float2(reinterpret_cast<__half2&>(v0.y));
                    float2 a2 = __half22float2(reinterpret_cast<__half2&>(v0.z));
                    float2 a3 = __half22float2(reinterpret_cast<__half2&>(v0.w));
                    acc[0] = fmaf(p0.x, a0.x, acc[0]); acc[1] = fmaf(p0.x, a0.y, acc[1]);
                    acc[2] = fmaf(p0.x, a1.x, acc[2]); acc[3] = fmaf(p0.x, a1.y, acc[3]);
                    acc[4] = fmaf(p0.x, a2.x, acc[4]); acc[5] = fmaf(p0.x, a2.y, acc[5]);
                    acc[6] = fmaf(p0.x, a3.x, acc[6]); acc[7] = fmaf(p0.x, a3.y, acc[7]);
                }
                __syncwarp(hmask);
            }
            // denominator allreduce within the half-warp
#pragma unroll
            for (int o = 8; o; o >>= 1) {
                se0 += __shfl_xor_sync(hmask, se0, o);
                se1 += __shfl_xor_sync(hmask, se1, o);
                se2 += __shfl_xor_sync(hmask, se2, o);
                se3 += __shfl_xor_sync(hmask, se3, o);
            }
            float invh = (hd == 0) ? 1.f / (se0 + 1e-16f)
                       : (hd == 1) ? 1.f / (se1 + 1e-16f)
                       : (hd == 2) ? 1.f / (se2 + 1e-16f)
                                   : 1.f / (se3 + 1e-16f);
#pragma unroll
            for (int j = 0; j < 8; j++) acc[j] *= invh;
            // mean over heads: lanes differing in bits 2,3 of hlane hold other heads
#pragma unroll
            for (int o = 4; o <= 8; o <<= 1) {
#pragma unroll
                for (int j = 0; j < 8; j++)
                    acc[j] += __shfl_xor_sync(hmask, acc[j], o);
            }
            if (valid && hlane < 4) {
                float4 r0, r1;
                r0.x = lk(0.25f * acc[0] + s_f[hlane * 8 + 0], 0.01f);
                r0.y = lk(0.25f * acc[1] + s_f[hlane * 8 + 1], 0.01f);
                r0.z = lk(0.25f * acc[2] + s_f[hlane * 8 + 2], 0.01f);
                r0.w = lk(0.25f * acc[3] + s_f[hlane * 8 + 3], 0.01f);
                r1.x = lk(0.25f * acc[4] + s_f[hlane * 8 + 4], 0.01f);
                r1.y = lk(0.25f * acc[5] + s_f[hlane * 8 + 5], 0.01f);
                r1.z = lk(0.25f * acc[6] + s_f[hlane * 8 + 6], 0.01f);
                r1.w = lk(0.25f * acc[7] + s_f[hlane * 8 + 7], 0.01f);
                float4* op = (float4*)(xout + node * 32);
                op[hlane * 2 + 0] = r0;
                op[hlane * 2 + 1] = r1;
            }
        }
        gsync(nb);
    }

    // ---- P5: tiled MLP (35->32->32->32->32->12) + fused compaction scatter --
    {
        const int W1o = 0, W2o = 1120, W3o = 2144, W4o = 3168, W5o = 4192;
        const int B1o = 4576, B2o = 4608, B3o = 4640, B4o = 4672, B5o = 4704;
        const int AO = 4736;                     // A[64][36]
        const int BO = 7040;                     // B[64][33]
        for (int i = tid; i < 1120; i += 256) s_f[W1o + i] = p.mW1[i];
        for (int i = tid; i < 1024; i += 256) {
            s_f[W2o + i] = p.mW2[i]; s_f[W3o + i] = p.mW3[i]; s_f[W4o + i] = p.mW4[i];
        }
        for (int i = tid; i < 384; i += 256) s_f[W5o + i] = p.mW5[i];
        if (tid < 32) {
            s_f[B1o + tid] = p.mb1[tid];
            s_f[B2o + tid] = p.mb2[tid];
            s_f[B3o + tid] = p.mb3[tid];
            s_f[B4o + tid] = p.mb4[tid];
        }
        if (tid < 12) s_f[B5o + tid] = p.mb5[tid];
        __syncthreads();

        const int tx = tid & 7, ty = tid >> 3;   // tx: 4 outs, ty: 2 nodes
        const int Nt = d_total[0];
        int ntile = (N + 63) / 64;
        for (int t = blockIdx.x; t < ntile; t += nb) {
            int n0 = t * 64, nn = min(64, N - n0);
            __syncthreads();
            for (int i = tid; i < nn * 8; i += 256) {
                float4 v = ((const float4*)(d_xa + n0 * 32))[i];
                int r = (i * 4) >> 5, c = (i * 4) & 31;
                float* ar = s_f + AO + r * 36 + 3 + c;
                ar[0] = v.x; ar[1] = v.y; ar[2] = v.z; ar[3] = v.w;
            }
            for (int i = tid; i < nn * 3; i += 256)
                s_f[AO + (i / 3) * 36 + (i % 3)] = p.x[n0 * 3 + i];
            __syncthreads();

            mlp_layer<35>(s_f, AO, 36, BO, 33, W1o, B1o, tx, ty, nn);  // L1: A->B
            mlp_layer<32>(s_f, BO, 33, AO, 36, W2o, B2o, tx, ty, nn);  // L2: B->A
            mlp_layer<32>(s_f, AO, 36, BO, 33, W3o, B3o, tx, ty, nn);  // L3: A->B
            mlp_layer<32>(s_f, BO, 33, AO, 36, W4o, B4o, tx, ty, nn);  // L4: B->A

            // L5 (32->12) warp-per-node + fused scatter to output
            for (int nl = wid; nl < nn; nl += 8) {
                int node = n0 + nl;
                float v = s_f[AO + nl * 36 + lane];
                float o = (lane < 12) ? s_f[B5o + lane] : 0.f;
#pragma unroll
                for (int k = 0; k < 32; k++) {
                    float vk = __shfl_sync(0xffffffffu, v, k);
                    if (lane < 12) o = fmaf(vk, s_f[W5o + k * 12 + lane], o);
                }
                int P = d_trank[node];
                if (d_tmask[node]) {
                    if (lane < 9) p.out[(size_t)P * 9 + lane] = o;
                    else if (lane < 12) p.out[(size_t)N * 9 + (size_t)P * 3 + (lane - 9)] = o;
                } else {
                    int Kp = node - P;
                    if (lane < 9) p.out[(size_t)Nt * 9 + (size_t)Kp * 9 + lane] = o;
                    else if (lane < 12)
                        p.out[(size_t)N * 9 + (size_t)Nt * 3 + (size_t)Kp * 3 + (lane - 9)] = o;
                }
            }
        }
    }
}

// ---------------- host ------------------------------------------------------
extern "C" void kernel_launch(void* const* d_in, const int* in_sizes, int n_in,
                              void* d_out, int out_size) {
    Params p;
    p.x  = (const float*)d_in[0];
    p.ei = d_in[1];
    p.W0 = (const float*)d_in[3];  p.aS0 = (const float*)d_in[4];
    p.aD0 = (const float*)d_in[5]; p.b0 = (const float*)d_in[6];
    p.W1 = (const float*)d_in[7];  p.aS1 = (const float*)d_in[8];
    p.aD1 = (const float*)d_in[9]; p.b1 = (const float*)d_in[10];
    p.W2 = (const float*)d_in[11]; p.aS2 = (const float*)d_in[12];
    p.aD2 = (const float*)d_in[13]; p.b2 = (const float*)d_in[14];
    p.mW1 = (const float*)d_in[15]; p.mb1 = (const float*)d_in[16];
    p.mW2 = (const float*)d_in[17]; p.mb2 = (const float*)d_in[18];
    p.mW3 = (const float*)d_in[19]; p.mb3 = (const float*)d_in[20];
    p.mW4 = (const float*)d_in[21]; p.mb4 = (const float*)d_in[22];
    p.mW5 = (const float*)d_in[23]; p.mb5 = (const float*)d_in[24];
    p.out = (float*)d_out;
    p.N = in_sizes[0] / 3;
    p.E = in_sizes[1] / 2;

    int dev = 0;
    cudaGetDevice(&dev);
    int nsm = 0;
    cudaDeviceGetAttribute(&nsm, cudaDevAttrMultiProcessorCount, dev);
    int maxb = 0;
    cudaOccupancyMaxActiveBlocksPerMultiprocessor(&maxb, k_mega, 256, 0);
    if (maxb < 1) maxb = 1;
    int grid = nsm * maxb;
    if (grid > 1024) grid = 1024;   // P2b block-0 scan handles <= 1024 block sums
    if (grid < 2) grid = 2;

    k_mega<<<grid, 256>>>(p);
}

// round 14
// speedup vs baseline: 1.4687x; 1.4687x over previous
#include <cuda_runtime.h>
#include <cuda_fp16.h>

// Problem constants (dataset: N=100000, E=800000, D=3, H=4, F=32)
#define NMAX 100000
#define EMAX 800000
#define ETMAX (NMAX + EMAX)

// ---------------- device scratch (static: no allocation allowed) -------------
__device__ __half d_hh[(size_t)NMAX * 128];    // per-layer hidden [N,4,32] fp16
__device__ float4 d_as[NMAX];                  // attention src logits [N,4]
__device__ float4 d_ad[NMAX];                  // attention dst logits [N,4]
__device__ float  d_xa[(size_t)NMAX * 32];     // layer outputs ping (fp32)
__device__ float  d_xb[(size_t)NMAX * 32];     // layer outputs pong (fp32)
__device__ int    d_rowptr[NMAX + 1];
__device__ int    d_cnt[NMAX];
__device__ int    d_wp[NMAX];
__device__ int    d_col[ETMAX];
__device__ int    d_tmask[NMAX];
__device__ int    d_trank[NMAX];
__device__ int    d_bsums0[1024];
__device__ int    d_bsums1[1024];
__device__ int    d_total[1];
__device__ int    d_is64[1];

// grid barrier state (self-resetting; generation persists across calls)
__device__ unsigned d_barcnt = 0;
__device__ unsigned d_bargen = 0;

__device__ __forceinline__ void gsync(int nb) {
    __syncthreads();
    if (threadIdx.x == 0) {
        __threadfence();
        unsigned g = d_bargen;
        unsigned a = atomicAdd(&d_barcnt, 1u);
        if (a == (unsigned)nb - 1u) {
            d_barcnt = 0;
            __threadfence();
            atomicAdd(&d_bargen, 1u);
        } else {
            while (atomicAdd(&d_bargen, 0u) == g) __nanosleep(128);
        }
        __threadfence();
    }
    __syncthreads();
}

__device__ __forceinline__ float lk(float v, float s) { return v >= 0.f ? v : s * v; }

__device__ __forceinline__ int eidx(const void* ei, int i) {
    if (d_is64[0]) return (int)((const long long*)ei)[i];
    return ((const int*)ei)[i];
}

// 256-wide exclusive scan in shared ints; exclusive prefix returned; total in s[255]
__device__ __forceinline__ int bscan(int v, int* s) {
    int tid = threadIdx.x;
    s[tid] = v;
    __syncthreads();
    for (int off = 1; off < 256; off <<= 1) {
        int t = (tid >= off) ? s[tid - off] : 0;
        __syncthreads();
        s[tid] += t;
        __syncthreads();
    }
    return s[tid] - v;
}

// One MLP GEMM layer on a 64-node tile held in shared memory.
template <int K>
__device__ __forceinline__ void mlp_layer(float* s, int inO, int inS, int outO, int outS,
                                          int wO, int bO, int tx, int ty, int nn) {
    float a0[4], a1[4];
#pragma unroll
    for (int j = 0; j < 4; j++) { a0[j] = s[bO + tx * 4 + j]; a1[j] = a0[j]; }
#pragma unroll
    for (int k = 0; k < K; k++) {
        float4 w = *(const float4*)&s[wO + k * 32 + tx * 4];
        float x0 = s[inO + (ty * 2) * inS + k];
        float x1 = s[inO + (ty * 2 + 1) * inS + k];
        a0[0] = fmaf(x0, w.x, a0[0]); a1[0] = fmaf(x1, w.x, a1[0]);
        a0[1] = fmaf(x0, w.y, a0[1]); a1[1] = fmaf(x1, w.y, a1[1]);
        a0[2] = fmaf(x0, w.z, a0[2]); a1[2] = fmaf(x1, w.z, a1[2]);
        a0[3] = fmaf(x0, w.w, a0[3]); a1[3] = fmaf(x1, w.w, a1[3]);
    }
    __syncthreads();
    if (ty * 2 < nn) {
#pragma unroll
        for (int j = 0; j < 4; j++) s[outO + (ty * 2) * outS + tx * 4 + j] = lk(a0[j], 0.01f);
    }
    if (ty * 2 + 1 < nn) {
#pragma unroll
        for (int j = 0; j < 4; j++) s[outO + (ty * 2 + 1) * outS + tx * 4 + j] = lk(a1[j], 0.01f);
    }
    __syncthreads();
}

struct Params {
    const float* x; const void* ei;
    const float* W0;  const float* W1;  const float* W2;
    const float* aS0; const float* aS1; const float* aS2;
    const float* aD0; const float* aD1; const float* aD2;
    const float* b0;  const float* b1;  const float* b2;
    const float* mW1; const float* mb1; const float* mW2; const float* mb2;
    const float* mW3; const float* mb3; const float* mW4; const float* mb4;
    const float* mW5; const float* mb5;
    float* out; int N; int E;
};

__global__ __launch_bounds__(256, 4) void k_mega(Params p) {
    __shared__ float s_f[9216];
    int* s_i = (int*)s_f;
    const int tid = threadIdx.x;
    const int nb = gridDim.x;
    const int gthreads = nb * 256;
    const int gid = blockIdx.x * 256 + tid;
    const int lane = tid & 31;
    const int wid = tid >> 5;
    const int gw = blockIdx.x * 8 + wid;
    const int nw = nb * 8;
    const int N = p.N, E = p.E, ET = E + N;
    const int R = (N + nb - 1) / nb;

    // ---- P0: init counters + tower mask; detect edge dtype -----------------
    for (int i = gid; i < N; i += gthreads) {
        d_cnt[i] = 0;
        d_tmask[i] = (p.x[i * 3] == 0.0f) ? 1 : 0;
    }
    if (blockIdx.x == 0) {
        int bad = 0;
        if (tid < 128) bad = (((const int*)p.ei)[2 * tid + 1] != 0) ? 1 : 0;
        s_i[tid] = bad;
        __syncthreads();
        if (tid == 0) {
            int any = 0;
            for (int i = 0; i < 128; i++) any |= s_i[i];
            d_is64[0] = any ? 0 : 1;
        }
    }
    gsync(nb);

    // ---- P1: degree count ---------------------------------------------------
    for (int e = gid; e < ET; e += gthreads) {
        int dst = (e < E) ? eidx(p.ei, E + e) : (e - E);
        atomicAdd(&d_cnt[dst], 1);
    }
    gsync(nb);

    // ---- P2a: per-block range sums (cnt and tmask) --------------------------
    {
        int lo = blockIdx.x * R, hi = min(N, lo + R);
        int s0 = 0, s1 = 0;
        for (int i = lo + tid; i < hi; i += 256) { s0 += d_cnt[i]; s1 += d_tmask[i]; }
#pragma unroll
        for (int o = 16; o; o >>= 1) {
            s0 += __shfl_xor_sync(0xffffffffu, s0, o);
            s1 += __shfl_xor_sync(0xffffffffu, s1, o);
        }
        if (lane == 0) { s_i[wid] = s0; s_i[8 + wid] = s1; }
        __syncthreads();
        if (tid == 0) {
            int a = 0, b = 0;
            for (int w = 0; w < 8; w++) { a += s_i[w]; b += s_i[8 + w]; }
            d_bsums0[blockIdx.x] = a; d_bsums1[blockIdx.x] = b;
        }
    }
    gsync(nb);

    // ---- P2b: block 0 scans the block sums ----------------------------------
    if (blockIdx.x == 0) {
        for (int arr = 0; arr < 2; arr++) {
            int* bs = arr ? d_bsums1 : d_bsums0;
            int carry = 0;
            for (int c = 0; c < nb; c += 256) {
                int i = c + tid;
                int v = (i < nb) ? bs[i] : 0;
                int ex = bscan(v, s_i);
                int tot = s_i[255];
                if (i < nb) bs[i] = carry + ex;
                carry += tot;
                __syncthreads();
            }
            if (tid == 0) { if (arr == 0) d_rowptr[N] = carry; else d_total[0] = carry; }
        }
    }
    gsync(nb);

    // ---- P2c: per-block local scan + global offset --------------------------
    {
        int lo = blockIdx.x * R, hi = min(N, lo + R);
        for (int arr = 0; arr < 2; arr++) {
            const int* in = arr ? d_tmask : d_cnt;
            int carry = arr ? d_bsums1[blockIdx.x] : d_bsums0[blockIdx.x];
            for (int c = lo; c < hi; c += 256) {
                int i = c + tid;
                int v = (i < hi) ? in[i] : 0;
                int ex = bscan(v, s_i);
                int tot = s_i[255];
                if (i < hi) {
                    int o = carry + ex;
                    if (arr == 0) { d_rowptr[i] = o; d_wp[i] = o; }
                    else d_trank[i] = o;
                }
                carry += tot;
                __syncthreads();
            }
        }
    }
    gsync(nb);

    // ---- P3: CSR fill -------------------------------------------------------
    for (int e = gid; e < ET; e += gthreads) {
        int src, dst;
        if (e < E) { src = eidx(p.ei, e); dst = eidx(p.ei, E + e); }
        else       { src = dst = e - E; }
        int pp = atomicAdd(&d_wp[dst], 1);
        d_col[pp] = src;
    }
    gsync(nb);

    // ---- P4: three GAT layers ----------------------------------------------
    for (int L = 0; L < 3; L++) {
        const int din = (L == 0) ? 3 : 32;
        const float* W  = (L == 0) ? p.W0  : (L == 1) ? p.W1  : p.W2;
        const float* aS = (L == 0) ? p.aS0 : (L == 1) ? p.aS1 : p.aS2;
        const float* aD = (L == 0) ? p.aD0 : (L == 1) ? p.aD1 : p.aD2;
        const float* bs = (L == 0) ? p.b0  : (L == 1) ? p.b1  : p.b2;
        const float* xin = (L == 0) ? p.x : (L == 1) ? d_xa : d_xb;
        float* xout = (L == 1) ? d_xb : d_xa;

        // P4a: h = x@W fused with attention logits (fp32 accs; h stored fp16)
        for (int i = tid; i < din * 128; i += 256) s_f[i] = W[i];
        if (tid < 128) { s_f[4096 + tid] = aS[tid]; s_f[4224 + tid] = aD[tid]; }
        __syncthreads();

        if (din == 3) {
            for (int node = gw; node < N; node += nw) {
                float xr = (lane < 3) ? xin[node * 3 + lane] : 0.f;
                float asv[4], adv[4];
#pragma unroll
                for (int hd4 = 0; hd4 < 4; hd4++) {
                    float s = 0.f;
#pragma unroll
                    for (int k = 0; k < 3; k++)
                        s = fmaf(__shfl_sync(0xffffffffu, xr, k), s_f[k * 128 + hd4 * 32 + lane], s);
                    // pack lane pairs into half2 stores (even lanes write)
                    float s1 = __shfl_down_sync(0xffffffffu, s, 1);
                    if (!(lane & 1)) {
                        __half2 hv = __floats2half2_rn(s, s1);
                        *(__half2*)(d_hh + node * 128 + hd4 * 32 + lane) = hv;
                    }
                    float u = s * s_f[4096 + hd4 * 32 + lane];
                    float v = s * s_f[4224 + hd4 * 32 + lane];
#pragma unroll
                    for (int o = 16; o; o >>= 1) {
                        u += __shfl_xor_sync(0xffffffffu, u, o);
                        v += __shfl_xor_sync(0xffffffffu, v, o);
                    }
                    asv[hd4] = u; adv[hd4] = v;
                }
                if (lane == 0) {
                    d_as[node] = make_float4(asv[0], asv[1], asv[2], asv[3]);
                    d_ad[node] = make_float4(adv[0], adv[1], adv[2], adv[3]);
                }
            }
        } else {
            // tiled GEMM: 32-node x 128-out tile, thread = 2 nodes x 8 outs
            const int XO = 4352;                 // Xs[32][33]
            const int tx = tid & 15, ty = tid >> 4;
            int ntile = (N + 31) / 32;
            for (int t = blockIdx.x; t < ntile; t += nb) {
                int n0 = t * 32, nn = min(32, N - n0);
                __syncthreads();
                for (int i = tid; i < nn * 8; i += 256) {
                    float4 v = ((const float4*)(xin + n0 * 32))[i];
                    int r = (i * 4) >> 5, c = (i * 4) & 31;
                    float* xr = s_f + XO + r * 33 + c;
                    xr[0] = v.x; xr[1] = v.y; xr[2] = v.z; xr[3] = v.w;
                }
                __syncthreads();
                float acc[2][8];
#pragma unroll
                for (int i = 0; i < 2; i++)
#pragma unroll
                    for (int j = 0; j < 8; j++) acc[i][j] = 0.f;
#pragma unroll
                for (int k = 0; k < 32; k++) {
                    float4 w0 = *(const float4*)&s_f[k * 128 + tx * 8];
                    float4 w1 = *(const float4*)&s_f[k * 128 + tx * 8 + 4];
                    float x0 = s_f[XO + (ty * 2) * 33 + k];
                    float x1 = s_f[XO + (ty * 2 + 1) * 33 + k];
                    acc[0][0] = fmaf(x0, w0.x, acc[0][0]); acc[1][0] = fmaf(x1, w0.x, acc[1][0]);
                    acc[0][1] = fmaf(x0, w0.y, acc[0][1]); acc[1][1] = fmaf(x1, w0.y, acc[1][1]);
                    acc[0][2] = fmaf(x0, w0.z, acc[0][2]); acc[1][2] = fmaf(x1, w0.z, acc[1][2]);
                    acc[0][3] = fmaf(x0, w0.w, acc[0][3]); acc[1][3] = fmaf(x1, w0.w, acc[1][3]);
                    acc[0][4] = fmaf(x0, w1.x, acc[0][4]); acc[1][4] = fmaf(x1, w1.x, acc[1][4]);
                    acc[0][5] = fmaf(x0, w1.y, acc[0][5]); acc[1][5] = fmaf(x1, w1.y, acc[1][5]);
                    acc[0][6] = fmaf(x0, w1.z, acc[0][6]); acc[1][6] = fmaf(x1, w1.z, acc[1][6]);
                    acc[0][7] = fmaf(x0, w1.w, acc[0][7]); acc[1][7] = fmaf(x1, w1.w, acc[1][7]);
                }
#pragma unroll
                for (int i = 0; i < 2; i++) {
                    int nl = ty * 2 + i;
                    int node = n0 + nl;
                    bool ok = nl < nn;
                    if (ok) {
                        __half2 q0 = __floats2half2_rn(acc[i][0], acc[i][1]);
                        __half2 q1 = __floats2half2_rn(acc[i][2], acc[i][3]);
                        __half2 q2 = __floats2half2_rn(acc[i][4], acc[i][5]);
                        __half2 q3 = __floats2half2_rn(acc[i][6], acc[i][7]);
                        uint4 pk;
                        pk.x = reinterpret_cast<unsigned&>(q0);
                        pk.y = reinterpret_cast<unsigned&>(q1);
                        pk.z = reinterpret_cast<unsigned&>(q2);
                        pk.w = reinterpret_cast<unsigned&>(q3);
                        *(uint4*)(d_hh + node * 128 + tx * 8) = pk;
                    }
                    float u = 0.f, v = 0.f;
#pragma unroll
                    for (int j = 0; j < 8; j++) {
                        u = fmaf(acc[i][j], s_f[4096 + tx * 8 + j], u);
                        v = fmaf(acc[i][j], s_f[4224 + tx * 8 + j], v);
                    }
                    u += __shfl_xor_sync(0xffffffffu, u, 1);
                    u += __shfl_xor_sync(0xffffffffu, u, 2);
                    v += __shfl_xor_sync(0xffffffffu, v, 1);
                    v += __shfl_xor_sync(0xffffffffu, v, 2);
                    if (ok && (tid & 3) == 0) {
                        int head = tx >> 2;
                        ((float*)&d_as[node])[head] = u;
                        ((float*)&d_ad[node])[head] = v;
                    }
                }
            }
        }
        gsync(nb);

        // P4c: warp per node; single-pass exp + gather, normalize after.
        // Logits O(+-5): exp cannot overflow; softmax is shift-invariant, and
        // (sum ex*h)/(sum ex + 1e-16) == sum (ex/denom)*h exactly in math.
        // h read as fp16 (256B/row), alphas & accumulation in fp32.
        // Denominator accumulated redundantly on every lane inside the serial
        // gather loop (each lane reads ex[e][hd] anyway) -> no allreduce.
        if (tid < 32) s_f[tid] = bs[tid];
        __syncthreads();
        const int hd = lane >> 3;                 // 8 lanes per head
        const int loff = hd * 32 + (lane & 7) * 4;  // halfs offset within row
        // packed per-warp buffer: pbuf[hd*33 + e] = {ex[hd], col-as-bits}
        float2* pbuf = (float2*)(s_f + 128) + wid * 144;
        const float2* pbh = pbuf + hd * 33;
        for (int node = gw; node < N; node += nw) {
            int beg = d_rowptr[node], end = d_rowptr[node + 1];
            float4 ad = d_ad[node];
            float4 acc0 = make_float4(0.f, 0.f, 0.f, 0.f);
            float4 acc1 = make_float4(0.f, 0.f, 0.f, 0.f);
            float seh = 0.f;
            for (int base = beg; base < end; base += 32) {
                int m = min(32, end - base);
                if (lane < m) {
                    int c = d_col[base + lane];
                    float4 a = d_as[c];
                    float4 ex;
                    ex.x = __expf(lk(a.x + ad.x, 0.2f));
                    ex.y = __expf(lk(a.y + ad.y, 0.2f));
                    ex.z = __expf(lk(a.z + ad.z, 0.2f));
                    ex.w = __expf(lk(a.w + ad.w, 0.2f));
                    float cf = __int_as_float(c);
                    pbuf[0 * 33 + lane] = make_float2(ex.x, cf);
                    pbuf[1 * 33 + lane] = make_float2(ex.y, cf);
                    pbuf[2 * 33 + lane] = make_float2(ex.z, cf);
                    pbuf[3 * 33 + lane] = make_float2(ex.w, cf);
                }
                __syncwarp();
                int e = 0;
                for (; e + 3 < m; e += 4) {
                    float2 p0 = pbh[e + 0];
                    float2 p1 = pbh[e + 1];
                    float2 p2 = pbh[e + 2];
                    float2 p3 = pbh[e + 3];
                    uint2 v0 = *(const uint2*)(d_hh + __float_as_int(p0.y) * 128 + loff);
                    uint2 v1 = *(const uint2*)(d_hh + __float_as_int(p1.y) * 128 + loff);
                    uint2 v2 = *(const uint2*)(d_hh + __float_as_int(p2.y) * 128 + loff);
                    uint2 v3 = *(const uint2*)(d_hh + __float_as_int(p3.y) * 128 + loff);
                    seh += p0.x + p1.x + p2.x + p3.x;
                    float2 l0 = __half22float2(reinterpret_cast<__half2&>(v0.x));
                    float2 m0 = __half22float2(reinterpret_cast<__half2&>(v0.y));
                    float2 l1 = __half22float2(reinterpret_cast<__half2&>(v1.x));
                    float2 m1 = __half22float2(reinterpret_cast<__half2&>(v1.y));
                    float2 l2 = __half22float2(reinterpret_cast<__half2&>(v2.x));
                    float2 m2 = __half22float2(reinterpret_cast<__half2&>(v2.y));
                    float2 l3 = __half22float2(reinterpret_cast<__half2&>(v3.x));
                    float2 m3 = __half22float2(reinterpret_cast<__half2&>(v3.y));
                    acc0.x = fmaf(p0.x, l0.x, acc0.x); acc1.x = fmaf(p1.x, l1.x, acc1.x);
                    acc0.y = fmaf(p0.x, l0.y, acc0.y); acc1.y = fmaf(p1.x, l1.y, acc1.y);
                    acc0.z = fmaf(p0.x, m0.x, acc0.z); acc1.z = fmaf(p1.x, m1.x, acc1.z);
                    acc0.w = fmaf(p0.x, m0.y, acc0.w); acc1.w = fmaf(p1.x, m1.y, acc1.w);
                    acc0.x = fmaf(p2.x, l2.x, acc0.x); acc1.x = fmaf(p3.x, l3.x, acc1.x);
                    acc0.y = fmaf(p2.x, l2.y, acc0.y); acc1.y = fmaf(p3.x, l3.y, acc1.y);
                    acc0.z = fmaf(p2.x, m2.x, acc0.z); acc1.z = fmaf(p3.x, m3.x, acc1.z);
                    acc0.w = fmaf(p2.x, m2.y, acc0.w); acc1.w = fmaf(p3.x, m3.y, acc1.w);
                }
                for (; e < m; e++) {
                    float2 p0 = pbh[e];
                    uint2 v0 = *(const uint2*)(d_hh + __float_as_int(p0.y) * 128 + loff);
                    seh += p0.x;
                    float2 l0 = __half22float2(reinterpret_cast<__half2&>(v0.x));
                    float2 m0 = __half22float2(reinterpret_cast<__half2&>(v0.y));
                    acc0.x = fmaf(p0.x, l0.x, acc0.x);
                    acc0.y = fmaf(p0.x, l0.y, acc0.y);
                    acc0.z = fmaf(p0.x, m0.x, acc0.z);
                    acc0.w = fmaf(p0.x, m0.y, acc0.w);
                }
                __syncwarp();
            }
            float invh = 1.f / (seh + 1e-16f);
            acc0.x = (acc0.x + acc1.x) * invh;
            acc0.y = (acc0.y + acc1.y) * invh;
            acc0.z = (acc0.z + acc1.z) * invh;
            acc0.w = (acc0.w + acc1.w) * invh;
#pragma unroll
            for (int o = 8; o <= 16; o <<= 1) {
                acc0.x += __shfl_xor_sync(0xffffffffu, acc0.x, o);
                acc0.y += __shfl_xor_sync(0xffffffffu, acc0.y, o);
                acc0.z += __shfl_xor_sync(0xffffffffu, acc0.z, o);
                acc0.w += __shfl_xor_sync(0xffffffffu, acc0.w, o);
            }
            if (lane < 8) {
                float4 r;
                r.x = lk(0.25f * acc0.x + s_f[4 * lane + 0], 0.01f);
                r.y = lk(0.25f * acc0.y + s_f[4 * lane + 1], 0.01f);
                r.z = lk(0.25f * acc0.z + s_f[4 * lane + 2], 0.01f);
                r.w = lk(0.25f * acc0.w + s_f[4 * lane + 3], 0.01f);
                ((float4*)(xout + node * 32))[lane] = r;
            }
        }
        gsync(nb);
    }

    // ---- P5: tiled MLP (35->32->32->32->32->12) + fused compaction scatter --
    {
        const int W1o = 0, W2o = 1120, W3o = 2144, W4o = 3168, W5o = 4192;
        const int B1o = 4576, B2o = 4608, B3o = 4640, B4o = 4672, B5o = 4704;
        const int AO = 4736;                     // A[64][36]
        const int BO = 7040;                     // B[64][33]
        for (int i = tid; i < 1120; i += 256) s_f[W1o + i] = p.mW1[i];
        for (int i = tid; i < 1024; i += 256) {
            s_f[W2o + i] = p.mW2[i]; s_f[W3o + i] = p.mW3[i]; s_f[W4o + i] = p.mW4[i];
        }
        for (int i = tid; i < 384; i += 256) s_f[W5o + i] = p.mW5[i];
        if (tid < 32) {
            s_f[B1o + tid] = p.mb1[tid];
            s_f[B2o + tid] = p.mb2[tid];
            s_f[B3o + tid] = p.mb3[tid];
            s_f[B4o + tid] = p.mb4[tid];
        }
        if (tid < 12) s_f[B5o + tid] = p.mb5[tid];
        __syncthreads();

        const int tx = tid & 7, ty = tid >> 3;   // tx: 4 outs, ty: 2 nodes
        const int Nt = d_total[0];
        int ntile = (N + 63) / 64;
        for (int t = blockIdx.x; t < ntile; t += nb) {
            int n0 = t * 64, nn = min(64, N - n0);
            __syncthreads();
            for (int i = tid; i < nn * 8; i += 256) {
                float4 v = ((const float4*)(d_xa + n0 * 32))[i];
                int r = (i * 4) >> 5, c = (i * 4) & 31;
                float* ar = s_f + AO + r * 36 + 3 + c;
                ar[0] = v.x; ar[1] = v.y; ar[2] = v.z; ar[3] = v.w;
            }
            for (int i = tid; i < nn * 3; i += 256)
                s_f[AO + (i / 3) * 36 + (i % 3)] = p.x[n0 * 3 + i];
            __syncthreads();

            mlp_layer<35>(s_f, AO, 36, BO, 33, W1o, B1o, tx, ty, nn);  // L1: A->B
            mlp_layer<32>(s_f, BO, 33, AO, 36, W2o, B2o, tx, ty, nn);  // L2: B->A
            mlp_layer<32>(s_f, AO, 36, BO, 33, W3o, B3o, tx, ty, nn);  // L3: A->B
            mlp_layer<32>(s_f, BO, 33, AO, 36, W4o, B4o, tx, ty, nn);  // L4: B->A

            // L5 (32->12) warp-per-node + fused scatter to output
            for (int nl = wid; nl < nn; nl += 8) {
                int node = n0 + nl;
                float v = s_f[AO + nl * 36 + lane];
                float o = (lane < 12) ? s_f[B5o + lane] : 0.f;
#pragma unroll
                for (int k = 0; k < 32; k++) {
                    float vk = __shfl_sync(0xffffffffu, v, k);
                    if (lane < 12) o = fmaf(vk, s_f[W5o + k * 12 + lane], o);
                }
                int P = d_trank[node];
                if (d_tmask[node]) {
                    if (lane < 9) p.out[(size_t)P * 9 + lane] = o;
                    else if (lane < 12) p.out[(size_t)N * 9 + (size_t)P * 3 + (lane - 9)] = o;
                } else {
                    int Kp = node - P;
                    if (lane < 9) p.out[(size_t)Nt * 9 + (size_t)Kp * 9 + lane] = o;
                    else if (lane < 12)
                        p.out[(size_t)N * 9 + (size_t)Nt * 3 + (size_t)Kp * 3 + (lane - 9)] = o;
                }
            }
        }
    }
}

// ---------------- host ------------------------------------------------------
extern "C" void kernel_launch(void* const* d_in, const int* in_sizes, int n_in,
                              void* d_out, int out_size) {
    Params p;
    p.x  = (const float*)d_in[0];
    p.ei = d_in[1];
    p.W0 = (const float*)d_in[3];  p.aS0 = (const float*)d_in[4];
    p.aD0 = (const float*)d_in[5]; p.b0 = (const float*)d_in[6];
    p.W1 = (const float*)d_in[7];  p.aS1 = (const float*)d_in[8];
    p.aD1 = (const float*)d_in[9]; p.b1 = (const float*)d_in[10];
    p.W2 = (const float*)d_in[11]; p.aS2 = (const float*)d_in[12];
    p.aD2 = (const float*)d_in[13]; p.b2 = (const float*)d_in[14];
    p.mW1 = (const float*)d_in[15]; p.mb1 = (const float*)d_in[16];
    p.mW2 = (const float*)d_in[17]; p.mb2 = (const float*)d_in[18];
    p.mW3 = (const float*)d_in[19]; p.mb3 = (const float*)d_in[20];
    p.mW4 = (const float*)d_in[21]; p.mb4 = (const float*)d_in[22];
    p.mW5 = (const float*)d_in[23]; p.mb5 = (const float*)d_in[24];
    p.out = (float*)d_out;
    p.N = in_sizes[0] / 3;
    p.E = in_sizes[1] / 2;

    int dev = 0;
    cudaGetDevice(&dev);
    int nsm = 0;
    cudaDeviceGetAttribute(&nsm, cudaDevAttrMultiProcessorCount, dev);
    int maxb = 0;
    cudaOccupancyMaxActiveBlocksPerMultiprocessor(&maxb, k_mega, 256, 0);
    if (maxb < 1) maxb = 1;
    int grid = nsm * maxb;
    if (grid > 1024) grid = 1024;   // P2b block-0 scan handles <= 1024 block sums
    if (grid < 2) grid = 2;

    k_mega<<<grid, 256>>>(p);
}